// round 5
// baseline (speedup 1.0000x reference)
#include <cuda_runtime.h>
#include <cstdint>

#define NU 100000
#define NS 50000
#define NE 600000
#define DIN 128
#define H1 128
#define H2 64

// ---------------- scratch (device globals; no allocations allowed) ----------
__device__ float g_mean_user[NU * DIN];
__device__ float g_mean_song[NS * DIN];
__device__ float g_h_user[NU * H1];
__device__ float g_h_song[NS * H1];
__device__ int g_cnt_user[NU];
__device__ int g_cnt_song[NS];
__device__ int g_off_user[NU];    // raw per-block inclusive scan
__device__ int g_off_song[NS];
__device__ int g_fin_user[NU];    // final inclusive offsets
__device__ int g_fin_song[NS];
__device__ int g_cur_user[NU];    // bin cursors (exclusive offsets)
__device__ int g_cur_song[NS];
__device__ int g_srt_us[NE];
__device__ int g_srt_su[NE];
__device__ int g_part[256];

// ---------------- packed f32x2 helpers --------------------------------------
__device__ __forceinline__ void unpack2(unsigned long long v, float& lo, float& hi) {
    asm("mov.b64 {%0, %1}, %2;" : "=f"(lo), "=f"(hi) : "l"(v));
}
__device__ __forceinline__ unsigned long long ffma2(unsigned long long a,
                                                    unsigned long long b,
                                                    unsigned long long c) {
    unsigned long long d;
    asm("fma.rn.f32x2 %0, %1, %2, %3;" : "=l"(d) : "l"(a), "l"(b), "l"(c));
    return d;
}

// ---------------- CSR build --------------------------------------------------
__global__ void zero_int2(int* a, int na, int* b, int nb) {
    int i = blockIdx.x * blockDim.x + threadIdx.x;
    if (i < na) a[i] = 0;
    if (i < nb) b[i] = 0;
}

__global__ void count_kernel(const int* __restrict__ us_dst,
                             const int* __restrict__ su_dst,
                             int* __restrict__ cnt_song,
                             int* __restrict__ cnt_user, int n) {
    int i = blockIdx.x * blockDim.x + threadIdx.x;
    if (i < n) {
        atomicAdd(&cnt_song[us_dst[i]], 1);
        atomicAdd(&cnt_user[su_dst[i]], 1);
    }
}

// per-block inclusive scan for both node types in one launch
__global__ void scan_block_dual(const int* __restrict__ cs, int* __restrict__ os,
                                int ns, const int* __restrict__ cu,
                                int* __restrict__ ou, int nu,
                                int* __restrict__ partials, int nbs) {
    __shared__ int s[1024];
    int b = blockIdx.x;
    const int* in;
    int* out;
    int n, lb;
    if (b < nbs) { in = cs; out = os; n = ns; lb = b; }
    else { in = cu; out = ou; n = nu; lb = b - nbs; }
    int gid = lb * 1024 + threadIdx.x;
    s[threadIdx.x] = (gid < n) ? in[gid] : 0;
    __syncthreads();
#pragma unroll
    for (int d = 1; d < 1024; d <<= 1) {
        int t = (threadIdx.x >= d) ? s[threadIdx.x - d] : 0;
        __syncthreads();
        s[threadIdx.x] += t;
        __syncthreads();
    }
    if (gid < n) out[gid] = s[threadIdx.x];
    if (threadIdx.x == 1023) partials[b] = s[1023];
}

// scan partials for both segments in one block (na, nb <= 128)
__global__ void scan_partials_dual(int* p, int na, int nb) {
    __shared__ int s[128];
    int t = threadIdx.x;
    s[t] = (t < na) ? p[t] : 0;
    __syncthreads();
#pragma unroll
    for (int d = 1; d < 128; d <<= 1) {
        int v = (t >= d) ? s[t - d] : 0;
        __syncthreads();
        s[t] += v;
        __syncthreads();
    }
    if (t < na) p[t] = s[t];
    __syncthreads();
    s[t] = (t < nb) ? p[na + t] : 0;
    __syncthreads();
#pragma unroll
    for (int d = 1; d < 128; d <<= 1) {
        int v = (t >= d) ? s[t - d] : 0;
        __syncthreads();
        s[t] += v;
        __syncthreads();
    }
    if (t < nb) p[na + t] = s[t];
}

// finalize inclusive offsets + exclusive cursors for both node types
__global__ void scan_finish_dual(const int* __restrict__ rs, int* __restrict__ fs,
                                 int* __restrict__ curs, int ns,
                                 const int* __restrict__ ru, int* __restrict__ fu,
                                 int* __restrict__ curu, int nu,
                                 const int* __restrict__ partials, int nbs) {
    int i = blockIdx.x * blockDim.x + threadIdx.x;
    if (i < ns) {
        int b = i >> 10;
        fs[i] = rs[i] + ((b > 0) ? partials[b - 1] : 0);
        int c = 0;
        if (i > 0) {
            int j = i - 1, bj = j >> 10;
            c = rs[j] + ((bj > 0) ? partials[bj - 1] : 0);
        }
        curs[i] = c;
    }
    int u = i - ns;
    if (u >= 0 && u < nu) {
        int b = u >> 10;
        fu[u] = ru[u] + ((b > 0) ? partials[nbs + b - 1] : 0);
        int c = 0;
        if (u > 0) {
            int j = u - 1, bj = j >> 10;
            c = ru[j] + ((bj > 0) ? partials[nbs + bj - 1] : 0);
        }
        curu[u] = c;
    }
}

__global__ void bin_dual(const int* __restrict__ us_src,
                         const int* __restrict__ us_dst,
                         const int* __restrict__ su_src,
                         const int* __restrict__ su_dst,
                         int* __restrict__ cur_song, int* __restrict__ cur_user,
                         int* __restrict__ srt_us, int* __restrict__ srt_su,
                         int n) {
    int i = blockIdx.x * blockDim.x + threadIdx.x;
    if (i < n) {
        int p0 = atomicAdd(&cur_song[us_dst[i]], 1);
        srt_us[p0] = us_src[i];
        int p1 = atomicAdd(&cur_user[su_dst[i]], 1);
        srt_su[p1] = su_src[i];
    }
}

// ---------------- gather-mean, both node types in one launch -----------------
__global__ void gather_dual(const float* __restrict__ featA,
                            const int* __restrict__ srtA,
                            const int* __restrict__ offA,
                            float* __restrict__ meanA, int nA,
                            const float* __restrict__ featB,
                            const int* __restrict__ srtB,
                            const int* __restrict__ offB,
                            float* __restrict__ meanB, int nB) {
    int g = blockIdx.x * 8 + (threadIdx.x >> 5);
    const float* feat;
    const int* srt;
    const int* off;
    float* mean;
    int d;
    if (g < nA) {
        feat = featA; srt = srtA; off = offA; mean = meanA; d = g;
    } else {
        d = g - nA;
        if (d >= nB) return;
        feat = featB; srt = srtB; off = offB; mean = meanB;
    }
    int lane = threadIdx.x & 31;
    int start = (d > 0) ? off[d - 1] : 0;
    int end = off[d];
    float4 acc = make_float4(0.f, 0.f, 0.f, 0.f);
    int i = start;
    for (; i + 4 <= end; i += 4) {
        int s0 = srt[i], s1 = srt[i + 1], s2 = srt[i + 2], s3 = srt[i + 3];
        float4 a = *reinterpret_cast<const float4*>(feat + (size_t)s0 * DIN + lane * 4);
        float4 b = *reinterpret_cast<const float4*>(feat + (size_t)s1 * DIN + lane * 4);
        float4 c = *reinterpret_cast<const float4*>(feat + (size_t)s2 * DIN + lane * 4);
        float4 e = *reinterpret_cast<const float4*>(feat + (size_t)s3 * DIN + lane * 4);
        acc.x += (a.x + b.x) + (c.x + e.x);
        acc.y += (a.y + b.y) + (c.y + e.y);
        acc.z += (a.z + b.z) + (c.z + e.z);
        acc.w += (a.w + b.w) + (c.w + e.w);
    }
    for (; i < end; ++i) {
        int s0 = srt[i];
        float4 a = *reinterpret_cast<const float4*>(feat + (size_t)s0 * DIN + lane * 4);
        acc.x += a.x; acc.y += a.y; acc.z += a.z; acc.w += a.w;
    }
    int deg = end - start;
    float inv = 1.0f / (float)((deg > 0) ? deg : 1);
    acc.x *= inv; acc.y *= inv; acc.z *= inv; acc.w *= inv;
    *reinterpret_cast<float4*>(mean + (size_t)d * DIN + lane * 4) = acc;
}

// ---------------- fused dual SAGE GEMM ---------------------------------------
// One launch handles both node types (per-side weights). Duplicated-W smem so
// the f32x2 broadcast operand is a direct LDS (no MOV packs).
template <int NOUT>
__global__ void __launch_bounds__(256) sage_gemm_dual(
    const float* __restrict__ xdA, const float* __restrict__ mnA,
    const float* __restrict__ WsA, const float* __restrict__ WnA,
    const float* __restrict__ bA, float* __restrict__ outA, int MA, int nblkA,
    const float* __restrict__ xdB, const float* __restrict__ mnB,
    const float* __restrict__ WsB, const float* __restrict__ WnB,
    const float* __restrict__ bB, float* __restrict__ outB, int MB,
    int do_relu) {
    constexpr int NC = 8;
    constexpr int CG = NOUT / NC;  // 16 (H1) / 8 (H2)
    constexpr int RG = 256 / CG;   // 16 / 32
    constexpr int TM = 8;
    constexpr int NP = TM / 2;
    constexpr int BM = RG * TM;    // 128 / 256
    constexpr int BK = 16;
    constexpr int XS = BM + 2;

    __shared__ __align__(16) float sW2[BK][2 * NOUT];
    __shared__ __align__(16) float sX[BK][XS];

    const float* xdst;
    const float* mean;
    const float* Ws;
    const float* Wn;
    const float* bias;
    float* out;
    int M, bid;
    if ((int)blockIdx.x < nblkA) {
        xdst = xdA; mean = mnA; Ws = WsA; Wn = WnA; bias = bA; out = outA;
        M = MA; bid = blockIdx.x;
    } else {
        xdst = xdB; mean = mnB; Ws = WsB; Wn = WnB; bias = bB; out = outB;
        M = MB; bid = blockIdx.x - nblkA;
    }

    const int tid = threadIdx.x;
    const int row0 = bid * BM;
    const int cg = tid % CG;
    const int rg = tid / CG;
    const int n0 = cg * NC;
    const int r0 = rg * TM;

    unsigned long long acc[NP][NC];
#pragma unroll
    for (int i = 0; i < NP; i++)
#pragma unroll
        for (int j = 0; j < NC; j++) acc[i][j] = 0ull;

    for (int chunk = 0; chunk < 16; ++chunk) {
        const bool neigh = (chunk >= 8);
        const int kbase = (chunk & 7) * BK;
        const float* Wp = neigh ? Wn : Ws;
        const float* Xp = neigh ? mean : xdst;

        __syncthreads();
        // W chunk [BK x NOUT] -> duplicated pairs
#pragma unroll
        for (int i = 0; i < (BK * NOUT) / (4 * 256); i++) {
            int idx4 = (tid + i * 256) * 4;
            int k = idx4 / NOUT, nn = idx4 % NOUT;
            float4 w = *reinterpret_cast<const float4*>(
                &Wp[(size_t)(kbase + k) * NOUT + nn]);
            *reinterpret_cast<float4*>(&sW2[k][2 * nn]) =
                make_float4(w.x, w.x, w.y, w.y);
            *reinterpret_cast<float4*>(&sW2[k][2 * nn + 4]) =
                make_float4(w.z, w.z, w.w, w.w);
        }
        // X chunk [BM x BK] transposed into sX[k][r]
#pragma unroll
        for (int i = 0; i < (BM * BK) / (4 * 256); i++) {
            int idx = tid + i * 256;
            int r = idx / (BK / 4);
            int kq = idx % (BK / 4);
            int gr = row0 + r;
            float4 v = (gr < M) ? *reinterpret_cast<const float4*>(
                                      &Xp[(size_t)gr * DIN + kbase + kq * 4])
                                : make_float4(0.f, 0.f, 0.f, 0.f);
            sX[kq * 4 + 0][r] = v.x;
            sX[kq * 4 + 1][r] = v.y;
            sX[kq * 4 + 2][r] = v.z;
            sX[kq * 4 + 3][r] = v.w;
        }
        __syncthreads();

#pragma unroll
        for (int k = 0; k < BK; k++) {
            unsigned long long wd[NC];
#pragma unroll
            for (int t = 0; t < NC / 2; t++) {
                ulonglong2 wp = *reinterpret_cast<const ulonglong2*>(
                    &sW2[k][2 * n0 + 4 * t]);
                wd[2 * t] = wp.x;
                wd[2 * t + 1] = wp.y;
            }
            const unsigned long long* xrow =
                reinterpret_cast<const unsigned long long*>(&sX[k][r0]);
#pragma unroll
            for (int i = 0; i < NP; i++) {
                unsigned long long xp = xrow[i];
#pragma unroll
                for (int j = 0; j < NC; j++) acc[i][j] = ffma2(xp, wd[j], acc[i][j]);
            }
        }
    }

    // epilogue
    float bv[NC];
#pragma unroll
    for (int j = 0; j < NC; j += 4) {
        float4 b = *reinterpret_cast<const float4*>(&bias[n0 + j]);
        bv[j] = b.x; bv[j + 1] = b.y; bv[j + 2] = b.z; bv[j + 3] = b.w;
    }
#pragma unroll
    for (int i = 0; i < NP; i++) {
        float la[NC], lb[NC];
#pragma unroll
        for (int j = 0; j < NC; j++) {
            unpack2(acc[i][j], la[j], lb[j]);
            la[j] += bv[j];
            lb[j] += bv[j];
            if (do_relu) {
                la[j] = fmaxf(la[j], 0.0f);
                lb[j] = fmaxf(lb[j], 0.0f);
            }
        }
        int ra = row0 + r0 + 2 * i;
        int rb = ra + 1;
        if (ra < M) {
            float* p = out + (size_t)ra * NOUT + n0;
            *reinterpret_cast<float4*>(p) = make_float4(la[0], la[1], la[2], la[3]);
            *reinterpret_cast<float4*>(p + 4) =
                make_float4(la[4], la[5], la[6], la[7]);
        }
        if (rb < M) {
            float* p = out + (size_t)rb * NOUT + n0;
            *reinterpret_cast<float4*>(p) = make_float4(lb[0], lb[1], lb[2], lb[3]);
            *reinterpret_cast<float4*>(p + 4) =
                make_float4(lb[4], lb[5], lb[6], lb[7]);
        }
    }
}

// ---------------- host launch -----------------------------------------------
extern "C" void kernel_launch(void* const* d_in, const int* in_sizes, int n_in,
                              void* d_out, int out_size) {
    const float* x_user = (const float*)d_in[0];
    const float* x_song = (const float*)d_in[1];
    const int* us_src = (const int*)d_in[2];
    const int* us_dst = (const int*)d_in[3];
    const int* su_src = (const int*)d_in[4];
    const int* su_dst = (const int*)d_in[5];
    const float* W1_us_n = (const float*)d_in[6];
    const float* W1_us_s = (const float*)d_in[7];
    const float* b1_us = (const float*)d_in[8];
    const float* W1_su_n = (const float*)d_in[9];
    const float* W1_su_s = (const float*)d_in[10];
    const float* b1_su = (const float*)d_in[11];
    const float* W2_us_n = (const float*)d_in[12];
    const float* W2_us_s = (const float*)d_in[13];
    const float* b2_us = (const float*)d_in[14];
    const float* W2_su_n = (const float*)d_in[15];
    const float* W2_su_s = (const float*)d_in[16];
    const float* b2_su = (const float*)d_in[17];
    float* out = (float*)d_out;

    float *mean_user, *mean_song, *h_user, *h_song;
    int *cnt_user, *cnt_song, *off_user, *off_song, *fin_user, *fin_song;
    int *cur_user, *cur_song, *srt_us, *srt_su, *part;
    cudaGetSymbolAddress((void**)&mean_user, g_mean_user);
    cudaGetSymbolAddress((void**)&mean_song, g_mean_song);
    cudaGetSymbolAddress((void**)&h_user, g_h_user);
    cudaGetSymbolAddress((void**)&h_song, g_h_song);
    cudaGetSymbolAddress((void**)&cnt_user, g_cnt_user);
    cudaGetSymbolAddress((void**)&cnt_song, g_cnt_song);
    cudaGetSymbolAddress((void**)&off_user, g_off_user);
    cudaGetSymbolAddress((void**)&off_song, g_off_song);
    cudaGetSymbolAddress((void**)&fin_user, g_fin_user);
    cudaGetSymbolAddress((void**)&fin_song, g_fin_song);
    cudaGetSymbolAddress((void**)&cur_user, g_cur_user);
    cudaGetSymbolAddress((void**)&cur_song, g_cur_song);
    cudaGetSymbolAddress((void**)&srt_us, g_srt_us);
    cudaGetSymbolAddress((void**)&srt_su, g_srt_su);
    cudaGetSymbolAddress((void**)&part, g_part);

    const int NB_S = (NS + 1023) / 1024;  // 49
    const int NB_U = (NU + 1023) / 1024;  // 98

    // ---- CSR build (6 launches)
    zero_int2<<<(NU + 255) / 256, 256>>>(cnt_user, NU, cnt_song, NS);
    count_kernel<<<(NE + 255) / 256, 256>>>(us_dst, su_dst, cnt_song, cnt_user, NE);
    scan_block_dual<<<NB_S + NB_U, 1024>>>(cnt_song, off_song, NS, cnt_user,
                                           off_user, NU, part, NB_S);
    scan_partials_dual<<<1, 128>>>(part, NB_S, NB_U);
    scan_finish_dual<<<(NS + NU + 255) / 256, 256>>>(
        off_song, fin_song, cur_song, NS, off_user, fin_user, cur_user, NU,
        part, NB_S);
    bin_dual<<<(NE + 255) / 256, 256>>>(us_src, us_dst, su_src, su_dst, cur_song,
                                        cur_user, srt_us, srt_su, NE);

    // ---- layer 1
    gather_dual<<<(NS + NU + 7) / 8, 256>>>(x_user, srt_us, fin_song, mean_song,
                                            NS, x_song, srt_su, fin_user,
                                            mean_user, NU);
    {
        constexpr int BM1 = 128;
        int na = (NS + BM1 - 1) / BM1;
        int nb = (NU + BM1 - 1) / BM1;
        sage_gemm_dual<H1><<<na + nb, 256>>>(
            x_song, mean_song, W1_us_s, W1_us_n, b1_us, h_song, NS, na, x_user,
            mean_user, W1_su_s, W1_su_n, b1_su, h_user, NU, 1);
    }

    // ---- layer 2
    gather_dual<<<(NS + NU + 7) / 8, 256>>>(h_user, srt_us, fin_song, mean_song,
                                            NS, h_song, srt_su, fin_user,
                                            mean_user, NU);
    {
        constexpr int BM2 = 256;
        int na = (NS + BM2 - 1) / BM2;
        int nb = (NU + BM2 - 1) / BM2;
        sage_gemm_dual<H2><<<na + nb, 256>>>(
            h_song, mean_song, W2_us_s, W2_us_n, b2_us, out + (size_t)NU * H2,
            NS, na, h_user, mean_user, W2_su_s, W2_su_n, b2_su, out, NU, 0);
    }
}

// round 6
// speedup vs baseline: 2.3860x; 2.3860x over previous
#include <cuda_runtime.h>
#include <cstdint>

#define NU 100000
#define NS 50000
#define NE 600000
#define DIN 128
#define H1 128
#define H2 64

// ---------------- scratch (device globals; no allocations allowed) ----------
__device__ float g_mean_user[NU * DIN];
__device__ float g_mean_song[NS * DIN];
__device__ float g_h_user[NU * H1];
__device__ float g_h_song[NS * H1];
__device__ int g_cnt_user[NU];
__device__ int g_cnt_song[NS];
__device__ int g_off_user[NU];    // raw per-block inclusive scan
__device__ int g_off_song[NS];
__device__ int g_fin_user[NU];    // final inclusive offsets
__device__ int g_fin_song[NS];
__device__ int g_cur_user[NU];    // bin cursors (exclusive offsets)
__device__ int g_cur_song[NS];
__device__ int g_srt_us[NE];
__device__ int g_srt_su[NE];
__device__ int g_part[256];

// ---------------- packed f32x2 helpers --------------------------------------
__device__ __forceinline__ unsigned long long pack2(float lo, float hi) {
    unsigned long long r;
    asm("mov.b64 %0, {%1, %2};" : "=l"(r) : "f"(lo), "f"(hi));
    return r;
}
__device__ __forceinline__ void unpack2(unsigned long long v, float& lo, float& hi) {
    asm("mov.b64 {%0, %1}, %2;" : "=f"(lo), "=f"(hi) : "l"(v));
}
__device__ __forceinline__ unsigned long long ffma2(unsigned long long a,
                                                    unsigned long long b,
                                                    unsigned long long c) {
    unsigned long long d;
    asm("fma.rn.f32x2 %0, %1, %2, %3;" : "=l"(d) : "l"(a), "l"(b), "l"(c));
    return d;
}

// ---------------- CSR build --------------------------------------------------
__global__ void zero_int2(int* a, int na, int* b, int nb) {
    int i = blockIdx.x * blockDim.x + threadIdx.x;
    if (i < na) a[i] = 0;
    if (i < nb) b[i] = 0;
}

__global__ void count_kernel(const int* __restrict__ us_dst,
                             const int* __restrict__ su_dst,
                             int* __restrict__ cnt_song,
                             int* __restrict__ cnt_user, int n) {
    int i = blockIdx.x * blockDim.x + threadIdx.x;
    if (i < n) {
        atomicAdd(&cnt_song[us_dst[i]], 1);
        atomicAdd(&cnt_user[su_dst[i]], 1);
    }
}

// per-block inclusive scan for both node types in one launch
__global__ void scan_block_dual(const int* __restrict__ cs, int* __restrict__ os,
                                int ns, const int* __restrict__ cu,
                                int* __restrict__ ou, int nu,
                                int* __restrict__ partials, int nbs) {
    __shared__ int s[1024];
    int b = blockIdx.x;
    const int* in;
    int* out;
    int n, lb;
    if (b < nbs) { in = cs; out = os; n = ns; lb = b; }
    else { in = cu; out = ou; n = nu; lb = b - nbs; }
    int gid = lb * 1024 + threadIdx.x;
    s[threadIdx.x] = (gid < n) ? in[gid] : 0;
    __syncthreads();
#pragma unroll
    for (int d = 1; d < 1024; d <<= 1) {
        int t = (threadIdx.x >= d) ? s[threadIdx.x - d] : 0;
        __syncthreads();
        s[threadIdx.x] += t;
        __syncthreads();
    }
    if (gid < n) out[gid] = s[threadIdx.x];
    if (threadIdx.x == 1023) partials[b] = s[1023];
}

// scan partials for both segments in one block (na, nb <= 128)
__global__ void scan_partials_dual(int* p, int na, int nb) {
    __shared__ int s[128];
    int t = threadIdx.x;
    s[t] = (t < na) ? p[t] : 0;
    __syncthreads();
#pragma unroll
    for (int d = 1; d < 128; d <<= 1) {
        int v = (t >= d) ? s[t - d] : 0;
        __syncthreads();
        s[t] += v;
        __syncthreads();
    }
    if (t < na) p[t] = s[t];
    __syncthreads();
    s[t] = (t < nb) ? p[na + t] : 0;
    __syncthreads();
#pragma unroll
    for (int d = 1; d < 128; d <<= 1) {
        int v = (t >= d) ? s[t - d] : 0;
        __syncthreads();
        s[t] += v;
        __syncthreads();
    }
    if (t < nb) p[na + t] = s[t];
}

// finalize inclusive offsets + exclusive cursors for both node types
__global__ void scan_finish_dual(const int* __restrict__ rs, int* __restrict__ fs,
                                 int* __restrict__ curs, int ns,
                                 const int* __restrict__ ru, int* __restrict__ fu,
                                 int* __restrict__ curu, int nu,
                                 const int* __restrict__ partials, int nbs) {
    int i = blockIdx.x * blockDim.x + threadIdx.x;
    if (i < ns) {
        int b = i >> 10;
        fs[i] = rs[i] + ((b > 0) ? partials[b - 1] : 0);
        int c = 0;
        if (i > 0) {
            int j = i - 1, bj = j >> 10;
            c = rs[j] + ((bj > 0) ? partials[bj - 1] : 0);
        }
        curs[i] = c;
    }
    int u = i - ns;
    if (u >= 0 && u < nu) {
        int b = u >> 10;
        fu[u] = ru[u] + ((b > 0) ? partials[nbs + b - 1] : 0);
        int c = 0;
        if (u > 0) {
            int j = u - 1, bj = j >> 10;
            c = ru[j] + ((bj > 0) ? partials[nbs + bj - 1] : 0);
        }
        curu[u] = c;
    }
}

__global__ void bin_dual(const int* __restrict__ us_src,
                         const int* __restrict__ us_dst,
                         const int* __restrict__ su_src,
                         const int* __restrict__ su_dst,
                         int* __restrict__ cur_song, int* __restrict__ cur_user,
                         int* __restrict__ srt_us, int* __restrict__ srt_su,
                         int n) {
    int i = blockIdx.x * blockDim.x + threadIdx.x;
    if (i < n) {
        int p0 = atomicAdd(&cur_song[us_dst[i]], 1);
        srt_us[p0] = us_src[i];
        int p1 = atomicAdd(&cur_user[su_dst[i]], 1);
        srt_su[p1] = su_src[i];
    }
}

// ---------------- gather-mean, both node types in one launch -----------------
__global__ void gather_dual(const float* __restrict__ featA,
                            const int* __restrict__ srtA,
                            const int* __restrict__ offA,
                            float* __restrict__ meanA, int nA,
                            const float* __restrict__ featB,
                            const int* __restrict__ srtB,
                            const int* __restrict__ offB,
                            float* __restrict__ meanB, int nB) {
    int g = blockIdx.x * 8 + (threadIdx.x >> 5);
    const float* feat;
    const int* srt;
    const int* off;
    float* mean;
    int d;
    if (g < nA) {
        feat = featA; srt = srtA; off = offA; mean = meanA; d = g;
    } else {
        d = g - nA;
        if (d >= nB) return;
        feat = featB; srt = srtB; off = offB; mean = meanB;
    }
    int lane = threadIdx.x & 31;
    int start = (d > 0) ? off[d - 1] : 0;
    int end = off[d];
    float4 acc = make_float4(0.f, 0.f, 0.f, 0.f);
    int i = start;
    for (; i + 4 <= end; i += 4) {
        int s0 = srt[i], s1 = srt[i + 1], s2 = srt[i + 2], s3 = srt[i + 3];
        float4 a = *reinterpret_cast<const float4*>(feat + (size_t)s0 * DIN + lane * 4);
        float4 b = *reinterpret_cast<const float4*>(feat + (size_t)s1 * DIN + lane * 4);
        float4 c = *reinterpret_cast<const float4*>(feat + (size_t)s2 * DIN + lane * 4);
        float4 e = *reinterpret_cast<const float4*>(feat + (size_t)s3 * DIN + lane * 4);
        acc.x += (a.x + b.x) + (c.x + e.x);
        acc.y += (a.y + b.y) + (c.y + e.y);
        acc.z += (a.z + b.z) + (c.z + e.z);
        acc.w += (a.w + b.w) + (c.w + e.w);
    }
    for (; i < end; ++i) {
        int s0 = srt[i];
        float4 a = *reinterpret_cast<const float4*>(feat + (size_t)s0 * DIN + lane * 4);
        acc.x += a.x; acc.y += a.y; acc.z += a.z; acc.w += a.w;
    }
    int deg = end - start;
    float inv = 1.0f / (float)((deg > 0) ? deg : 1);
    acc.x *= inv; acc.y *= inv; acc.z *= inv; acc.w *= inv;
    *reinterpret_cast<float4*>(mean + (size_t)d * DIN + lane * 4) = acc;
}

// ---------------- fused dual SAGE GEMM (R4 inner loop + reg prefetch) --------
// out[r,:] = relu?( xdst[r,:] @ Ws + mean[r,:] @ Wn + bias )
// One launch covers both node types; per-block side dispatch.
template <int NOUT>
__global__ void __launch_bounds__(256, 2) sage_gemm_dual(
    const float* __restrict__ xdA, const float* __restrict__ mnA,
    const float* __restrict__ WsA, const float* __restrict__ WnA,
    const float* __restrict__ bA, float* __restrict__ outA, int MA, int nblkA,
    const float* __restrict__ xdB, const float* __restrict__ mnB,
    const float* __restrict__ WsB, const float* __restrict__ WnB,
    const float* __restrict__ bB, float* __restrict__ outB, int MB,
    int do_relu) {
    constexpr int NC = 8;
    constexpr int CG = NOUT / NC;  // 16 (H1) / 8 (H2)
    constexpr int RG = 256 / CG;   // 16 / 32
    constexpr int TM = 8;
    constexpr int NP = TM / 2;
    constexpr int BM = RG * TM;    // 128 / 256
    constexpr int BK = 16;
    constexpr int XS = BM + 2;
    constexpr int WI = (BK * NOUT) / (4 * 256);  // W float4 loads/thread: 2 / 1
    constexpr int XI = (BM * BK) / (4 * 256);    // X float4 loads/thread: 2 / 4

    __shared__ __align__(16) float sW[BK][NOUT];
    __shared__ __align__(16) float sX[BK][XS];

    const float* xdst;
    const float* mean;
    const float* Ws;
    const float* Wn;
    const float* bias;
    float* out;
    int M, bid;
    if ((int)blockIdx.x < nblkA) {
        xdst = xdA; mean = mnA; Ws = WsA; Wn = WnA; bias = bA; out = outA;
        M = MA; bid = blockIdx.x;
    } else {
        xdst = xdB; mean = mnB; Ws = WsB; Wn = WnB; bias = bB; out = outB;
        M = MB; bid = blockIdx.x - nblkA;
    }

    const int tid = threadIdx.x;
    const int row0 = bid * BM;
    const int cg = tid % CG;
    const int rg = tid / CG;
    const int n0 = cg * NC;
    const int r0 = rg * TM;

    unsigned long long acc[NP][NC];
#pragma unroll
    for (int i = 0; i < NP; i++)
#pragma unroll
        for (int j = 0; j < NC; j++) acc[i][j] = 0ull;

    float4 wreg[WI], xreg[XI];

    // prefetch chunk 0
    {
        const float* Wp = Ws;
        const float* Xp = xdst;
#pragma unroll
        for (int i = 0; i < WI; i++) {
            int idx4 = (tid + i * 256) * 4;
            int k = idx4 / NOUT, nn = idx4 % NOUT;
            wreg[i] = *reinterpret_cast<const float4*>(&Wp[(size_t)k * NOUT + nn]);
        }
#pragma unroll
        for (int i = 0; i < XI; i++) {
            int idx = tid + i * 256;
            int r = idx / (BK / 4);
            int kq = idx % (BK / 4);
            int gr = row0 + r;
            xreg[i] = (gr < M) ? *reinterpret_cast<const float4*>(
                                     &Xp[(size_t)gr * DIN + kq * 4])
                               : make_float4(0.f, 0.f, 0.f, 0.f);
        }
    }

    for (int chunk = 0; chunk < 16; ++chunk) {
        __syncthreads();
        // commit prefetched regs to smem
#pragma unroll
        for (int i = 0; i < WI; i++) {
            int idx4 = (tid + i * 256) * 4;
            int k = idx4 / NOUT, nn = idx4 % NOUT;
            *reinterpret_cast<float4*>(&sW[k][nn]) = wreg[i];
        }
#pragma unroll
        for (int i = 0; i < XI; i++) {
            int idx = tid + i * 256;
            int r = idx / (BK / 4);
            int kq = idx % (BK / 4);
            sX[kq * 4 + 0][r] = xreg[i].x;
            sX[kq * 4 + 1][r] = xreg[i].y;
            sX[kq * 4 + 2][r] = xreg[i].z;
            sX[kq * 4 + 3][r] = xreg[i].w;
        }
        __syncthreads();

        // prefetch next chunk (overlaps with compute below)
        if (chunk + 1 < 16) {
            const int nc = chunk + 1;
            const bool neigh = (nc >= 8);
            const int kbase = (nc & 7) * BK;
            const float* Wp = neigh ? Wn : Ws;
            const float* Xp = neigh ? mean : xdst;
#pragma unroll
            for (int i = 0; i < WI; i++) {
                int idx4 = (tid + i * 256) * 4;
                int k = idx4 / NOUT, nn = idx4 % NOUT;
                wreg[i] = *reinterpret_cast<const float4*>(
                    &Wp[(size_t)(kbase + k) * NOUT + nn]);
            }
#pragma unroll
            for (int i = 0; i < XI; i++) {
                int idx = tid + i * 256;
                int r = idx / (BK / 4);
                int kq = idx % (BK / 4);
                int gr = row0 + r;
                xreg[i] = (gr < M) ? *reinterpret_cast<const float4*>(
                                         &Xp[(size_t)gr * DIN + kbase + kq * 4])
                                   : make_float4(0.f, 0.f, 0.f, 0.f);
            }
        }

        // compute on current smem tiles (R4 inner loop, unchanged)
#pragma unroll
        for (int k = 0; k < BK; k++) {
            unsigned long long wd[NC];
#pragma unroll
            for (int j = 0; j < NC; j += 4) {
                float4 w = *reinterpret_cast<const float4*>(&sW[k][n0 + j]);
                wd[j + 0] = pack2(w.x, w.x);
                wd[j + 1] = pack2(w.y, w.y);
                wd[j + 2] = pack2(w.z, w.z);
                wd[j + 3] = pack2(w.w, w.w);
            }
#pragma unroll
            for (int i = 0; i < NP; i++) {
                unsigned long long xp =
                    *reinterpret_cast<const unsigned long long*>(
                        &sX[k][r0 + 2 * i]);
#pragma unroll
                for (int j = 0; j < NC; j++) acc[i][j] = ffma2(xp, wd[j], acc[i][j]);
            }
        }
    }

    // epilogue: bias (+relu), two rows per pair, 2x float4 stores per row
    float bv[NC];
#pragma unroll
    for (int j = 0; j < NC; j += 4) {
        float4 b = *reinterpret_cast<const float4*>(&bias[n0 + j]);
        bv[j] = b.x; bv[j + 1] = b.y; bv[j + 2] = b.z; bv[j + 3] = b.w;
    }
#pragma unroll
    for (int i = 0; i < NP; i++) {
        float la[NC], lb[NC];
#pragma unroll
        for (int j = 0; j < NC; j++) {
            unpack2(acc[i][j], la[j], lb[j]);
            la[j] += bv[j];
            lb[j] += bv[j];
            if (do_relu) {
                la[j] = fmaxf(la[j], 0.0f);
                lb[j] = fmaxf(lb[j], 0.0f);
            }
        }
        int ra = row0 + r0 + 2 * i;
        int rb = ra + 1;
        if (ra < M) {
            float* p = out + (size_t)ra * NOUT + n0;
            *reinterpret_cast<float4*>(p) = make_float4(la[0], la[1], la[2], la[3]);
            *reinterpret_cast<float4*>(p + 4) =
                make_float4(la[4], la[5], la[6], la[7]);
        }
        if (rb < M) {
            float* p = out + (size_t)rb * NOUT + n0;
            *reinterpret_cast<float4*>(p) = make_float4(lb[0], lb[1], lb[2], lb[3]);
            *reinterpret_cast<float4*>(p + 4) =
                make_float4(lb[4], lb[5], lb[6], lb[7]);
        }
    }
}

// ---------------- host launch -----------------------------------------------
extern "C" void kernel_launch(void* const* d_in, const int* in_sizes, int n_in,
                              void* d_out, int out_size) {
    const float* x_user = (const float*)d_in[0];
    const float* x_song = (const float*)d_in[1];
    const int* us_src = (const int*)d_in[2];
    const int* us_dst = (const int*)d_in[3];
    const int* su_src = (const int*)d_in[4];
    const int* su_dst = (const int*)d_in[5];
    const float* W1_us_n = (const float*)d_in[6];
    const float* W1_us_s = (const float*)d_in[7];
    const float* b1_us = (const float*)d_in[8];
    const float* W1_su_n = (const float*)d_in[9];
    const float* W1_su_s = (const float*)d_in[10];
    const float* b1_su = (const float*)d_in[11];
    const float* W2_us_n = (const float*)d_in[12];
    const float* W2_us_s = (const float*)d_in[13];
    const float* b2_us = (const float*)d_in[14];
    const float* W2_su_n = (const float*)d_in[15];
    const float* W2_su_s = (const float*)d_in[16];
    const float* b2_su = (const float*)d_in[17];
    float* out = (float*)d_out;

    float *mean_user, *mean_song, *h_user, *h_song;
    int *cnt_user, *cnt_song, *off_user, *off_song, *fin_user, *fin_song;
    int *cur_user, *cur_song, *srt_us, *srt_su, *part;
    cudaGetSymbolAddress((void**)&mean_user, g_mean_user);
    cudaGetSymbolAddress((void**)&mean_song, g_mean_song);
    cudaGetSymbolAddress((void**)&h_user, g_h_user);
    cudaGetSymbolAddress((void**)&h_song, g_h_song);
    cudaGetSymbolAddress((void**)&cnt_user, g_cnt_user);
    cudaGetSymbolAddress((void**)&cnt_song, g_cnt_song);
    cudaGetSymbolAddress((void**)&off_user, g_off_user);
    cudaGetSymbolAddress((void**)&off_song, g_off_song);
    cudaGetSymbolAddress((void**)&fin_user, g_fin_user);
    cudaGetSymbolAddress((void**)&fin_song, g_fin_song);
    cudaGetSymbolAddress((void**)&cur_user, g_cur_user);
    cudaGetSymbolAddress((void**)&cur_song, g_cur_song);
    cudaGetSymbolAddress((void**)&srt_us, g_srt_us);
    cudaGetSymbolAddress((void**)&srt_su, g_srt_su);
    cudaGetSymbolAddress((void**)&part, g_part);

    const int NB_S = (NS + 1023) / 1024;  // 49
    const int NB_U = (NU + 1023) / 1024;  // 98

    // ---- CSR build (6 launches)
    zero_int2<<<(NU + 255) / 256, 256>>>(cnt_user, NU, cnt_song, NS);
    count_kernel<<<(NE + 255) / 256, 256>>>(us_dst, su_dst, cnt_song, cnt_user, NE);
    scan_block_dual<<<NB_S + NB_U, 1024>>>(cnt_song, off_song, NS, cnt_user,
                                           off_user, NU, part, NB_S);
    scan_partials_dual<<<1, 128>>>(part, NB_S, NB_U);
    scan_finish_dual<<<(NS + NU + 255) / 256, 256>>>(
        off_song, fin_song, cur_song, NS, off_user, fin_user, cur_user, NU,
        part, NB_S);
    bin_dual<<<(NE + 255) / 256, 256>>>(us_src, us_dst, su_src, su_dst, cur_song,
                                        cur_user, srt_us, srt_su, NE);

    // ---- layer 1
    gather_dual<<<(NS + NU + 7) / 8, 256>>>(x_user, srt_us, fin_song, mean_song,
                                            NS, x_song, srt_su, fin_user,
                                            mean_user, NU);
    {
        constexpr int BM1 = 128;
        int na = (NS + BM1 - 1) / BM1;
        int nb = (NU + BM1 - 1) / BM1;
        sage_gemm_dual<H1><<<na + nb, 256>>>(
            x_song, mean_song, W1_us_s, W1_us_n, b1_us, h_song, NS, na, x_user,
            mean_user, W1_su_s, W1_su_n, b1_su, h_user, NU, 1);
    }

    // ---- layer 2
    gather_dual<<<(NS + NU + 7) / 8, 256>>>(h_user, srt_us, fin_song, mean_song,
                                            NS, h_song, srt_su, fin_user,
                                            mean_user, NU);
    {
        constexpr int BM2 = 256;
        int na = (NS + BM2 - 1) / BM2;
        int nb = (NU + BM2 - 1) / BM2;
        sage_gemm_dual<H2><<<na + nb, 256>>>(
            h_song, mean_song, W2_us_s, W2_us_n, b2_us, out + (size_t)NU * H2,
            NS, na, h_user, mean_user, W2_su_s, W2_su_n, b2_su, out, NU, 0);
    }
}

// round 8
// speedup vs baseline: 2.5207x; 1.0564x over previous
#include <cuda_runtime.h>
#include <cuda_bf16.h>
#include <cstdint>

#define NU 100000
#define NS 50000
#define NE 600000
#define DIN 128
#define H1 128
#define H2 64

// ---------------- scratch (device globals; no allocations allowed) ----------
__device__ float g_mean_user[NU * DIN];
__device__ float g_mean_song[NS * DIN];
__device__ float g_h_user[NU * H1];
__device__ float g_h_song[NS * H1];
__device__ int g_cnt_user[NU];
__device__ int g_cnt_song[NS];
__device__ int g_off_user[NU];
__device__ int g_off_song[NS];
__device__ int g_fin_user[NU];
__device__ int g_fin_song[NS];
__device__ int g_cur_user[NU];
__device__ int g_cur_song[NS];
__device__ int g_srt_us[NE];
__device__ int g_srt_su[NE];
__device__ int g_part[256];

// ---------------- helpers ----------------------------------------------------
__device__ __forceinline__ uint32_t smem_u32(const void* p) {
    uint32_t a;
    asm("{ .reg .u64 t; cvta.to.shared.u64 t, %1; cvt.u32.u64 %0, t; }"
        : "=r"(a) : "l"(p));
    return a;
}
__device__ __forceinline__ uint32_t sw128(uint32_t off) {
    return off ^ ((off >> 3) & 0x70);
}
__device__ __forceinline__ unsigned long long bfpack4(__nv_bfloat16 a,
                                                      __nv_bfloat16 b,
                                                      __nv_bfloat16 c,
                                                      __nv_bfloat16 d) {
    unsigned int lo = (unsigned int)__bfloat16_as_ushort(a) |
                      ((unsigned int)__bfloat16_as_ushort(b) << 16);
    unsigned int hi = (unsigned int)__bfloat16_as_ushort(c) |
                      ((unsigned int)__bfloat16_as_ushort(d) << 16);
    unsigned long long r;
    asm("mov.b64 %0, {%1, %2};" : "=l"(r) : "r"(lo), "r"(hi));
    return r;
}

__device__ __forceinline__ void ldsm_x4(uint32_t* r, uint32_t addr) {
    asm volatile(
        "ldmatrix.sync.aligned.m8n8.x4.shared.b16 {%0,%1,%2,%3}, [%4];"
        : "=r"(r[0]), "=r"(r[1]), "=r"(r[2]), "=r"(r[3]) : "r"(addr));
}
__device__ __forceinline__ void ldsm_x2(uint32_t* r, uint32_t addr) {
    asm volatile(
        "ldmatrix.sync.aligned.m8n8.x2.shared.b16 {%0,%1}, [%2];"
        : "=r"(r[0]), "=r"(r[1]) : "r"(addr));
}
__device__ __forceinline__ void mma16816(float* d, const uint32_t* a,
                                         const uint32_t* b) {
    asm volatile(
        "mma.sync.aligned.m16n8k16.row.col.f32.bf16.bf16.f32 "
        "{%0,%1,%2,%3}, {%4,%5,%6,%7}, {%8,%9}, {%0,%1,%2,%3};"
        : "+f"(d[0]), "+f"(d[1]), "+f"(d[2]), "+f"(d[3])
        : "r"(a[0]), "r"(a[1]), "r"(a[2]), "r"(a[3]), "r"(b[0]), "r"(b[1]));
}

// ---------------- CSR build (unchanged, proven) ------------------------------
__global__ void zero_int2(int* a, int na, int* b, int nb) {
    int i = blockIdx.x * blockDim.x + threadIdx.x;
    if (i < na) a[i] = 0;
    if (i < nb) b[i] = 0;
}

__global__ void count_kernel(const int* __restrict__ us_dst,
                             const int* __restrict__ su_dst,
                             int* __restrict__ cnt_song,
                             int* __restrict__ cnt_user, int n) {
    int i = blockIdx.x * blockDim.x + threadIdx.x;
    if (i < n) {
        atomicAdd(&cnt_song[us_dst[i]], 1);
        atomicAdd(&cnt_user[su_dst[i]], 1);
    }
}

__global__ void scan_block_dual(const int* __restrict__ cs, int* __restrict__ os,
                                int ns, const int* __restrict__ cu,
                                int* __restrict__ ou, int nu,
                                int* __restrict__ partials, int nbs) {
    __shared__ int s[1024];
    int b = blockIdx.x;
    const int* in;
    int* out;
    int n, lb;
    if (b < nbs) { in = cs; out = os; n = ns; lb = b; }
    else { in = cu; out = ou; n = nu; lb = b - nbs; }
    int gid = lb * 1024 + threadIdx.x;
    s[threadIdx.x] = (gid < n) ? in[gid] : 0;
    __syncthreads();
#pragma unroll
    for (int d = 1; d < 1024; d <<= 1) {
        int t = (threadIdx.x >= d) ? s[threadIdx.x - d] : 0;
        __syncthreads();
        s[threadIdx.x] += t;
        __syncthreads();
    }
    if (gid < n) out[gid] = s[threadIdx.x];
    if (threadIdx.x == 1023) partials[b] = s[1023];
}

__global__ void scan_partials_dual(int* p, int na, int nb) {
    __shared__ int s[128];
    int t = threadIdx.x;
    s[t] = (t < na) ? p[t] : 0;
    __syncthreads();
#pragma unroll
    for (int d = 1; d < 128; d <<= 1) {
        int v = (t >= d) ? s[t - d] : 0;
        __syncthreads();
        s[t] += v;
        __syncthreads();
    }
    if (t < na) p[t] = s[t];
    __syncthreads();
    s[t] = (t < nb) ? p[na + t] : 0;
    __syncthreads();
#pragma unroll
    for (int d = 1; d < 128; d <<= 1) {
        int v = (t >= d) ? s[t - d] : 0;
        __syncthreads();
        s[t] += v;
        __syncthreads();
    }
    if (t < nb) p[na + t] = s[t];
}

__global__ void scan_finish_dual(const int* __restrict__ rs, int* __restrict__ fs,
                                 int* __restrict__ curs, int ns,
                                 const int* __restrict__ ru, int* __restrict__ fu,
                                 int* __restrict__ curu, int nu,
                                 const int* __restrict__ partials, int nbs) {
    int i = blockIdx.x * blockDim.x + threadIdx.x;
    if (i < ns) {
        int b = i >> 10;
        fs[i] = rs[i] + ((b > 0) ? partials[b - 1] : 0);
        int c = 0;
        if (i > 0) {
            int j = i - 1, bj = j >> 10;
            c = rs[j] + ((bj > 0) ? partials[bj - 1] : 0);
        }
        curs[i] = c;
    }
    int u = i - ns;
    if (u >= 0 && u < nu) {
        int b = u >> 10;
        fu[u] = ru[u] + ((b > 0) ? partials[nbs + b - 1] : 0);
        int c = 0;
        if (u > 0) {
            int j = u - 1, bj = j >> 10;
            c = ru[j] + ((bj > 0) ? partials[nbs + bj - 1] : 0);
        }
        curu[u] = c;
    }
}

__global__ void bin_dual(const int* __restrict__ us_src,
                         const int* __restrict__ us_dst,
                         const int* __restrict__ su_src,
                         const int* __restrict__ su_dst,
                         int* __restrict__ cur_song, int* __restrict__ cur_user,
                         int* __restrict__ srt_us, int* __restrict__ srt_su,
                         int n) {
    int i = blockIdx.x * blockDim.x + threadIdx.x;
    if (i < n) {
        int p0 = atomicAdd(&cur_song[us_dst[i]], 1);
        srt_us[p0] = us_src[i];
        int p1 = atomicAdd(&cur_user[su_dst[i]], 1);
        srt_su[p1] = su_src[i];
    }
}

// ---------------- gather-mean (unchanged, proven) ----------------------------
__global__ void gather_dual(const float* __restrict__ featA,
                            const int* __restrict__ srtA,
                            const int* __restrict__ offA,
                            float* __restrict__ meanA, int nA,
                            const float* __restrict__ featB,
                            const int* __restrict__ srtB,
                            const int* __restrict__ offB,
                            float* __restrict__ meanB, int nB) {
    int g = blockIdx.x * 8 + (threadIdx.x >> 5);
    const float* feat;
    const int* srt;
    const int* off;
    float* mean;
    int d;
    if (g < nA) {
        feat = featA; srt = srtA; off = offA; mean = meanA; d = g;
    } else {
        d = g - nA;
        if (d >= nB) return;
        feat = featB; srt = srtB; off = offB; mean = meanB;
    }
    int lane = threadIdx.x & 31;
    int start = (d > 0) ? off[d - 1] : 0;
    int end = off[d];
    float4 acc = make_float4(0.f, 0.f, 0.f, 0.f);
    int i = start;
    for (; i + 4 <= end; i += 4) {
        int s0 = srt[i], s1 = srt[i + 1], s2 = srt[i + 2], s3 = srt[i + 3];
        float4 a = *reinterpret_cast<const float4*>(feat + (size_t)s0 * DIN + lane * 4);
        float4 b = *reinterpret_cast<const float4*>(feat + (size_t)s1 * DIN + lane * 4);
        float4 c = *reinterpret_cast<const float4*>(feat + (size_t)s2 * DIN + lane * 4);
        float4 e = *reinterpret_cast<const float4*>(feat + (size_t)s3 * DIN + lane * 4);
        acc.x += (a.x + b.x) + (c.x + e.x);
        acc.y += (a.y + b.y) + (c.y + e.y);
        acc.z += (a.z + b.z) + (c.z + e.z);
        acc.w += (a.w + b.w) + (c.w + e.w);
    }
    for (; i < end; ++i) {
        int s0 = srt[i];
        float4 a = *reinterpret_cast<const float4*>(feat + (size_t)s0 * DIN + lane * 4);
        acc.x += a.x; acc.y += a.y; acc.z += a.z; acc.w += a.w;
    }
    int deg = end - start;
    float inv = 1.0f / (float)((deg > 0) ? deg : 1);
    acc.x *= inv; acc.y *= inv; acc.z *= inv; acc.w *= inv;
    *reinterpret_cast<float4*>(mean + (size_t)d * DIN + lane * 4) = acc;
}

// ---------------- bf16-split tensor-core SAGE GEMM ---------------------------
// D[128, NOUT] = Xself@Ws + Xneigh@Wn, fp32 accum, via mma.sync bf16 hi/lo
// (3 passes: hi*hi + hi*lo + lo*hi). K=128 per operand, staged in 64-chunks.
template <int NOUT>
__global__ void __launch_bounds__(256) sage_gemm_mma(
    const float* __restrict__ xdA, const float* __restrict__ mnA,
    const float* __restrict__ WsA, const float* __restrict__ WnA,
    const float* __restrict__ bA, float* __restrict__ outA, int MA, int nblkA,
    const float* __restrict__ xdB, const float* __restrict__ mnB,
    const float* __restrict__ WsB, const float* __restrict__ WnB,
    const float* __restrict__ bB, float* __restrict__ outB, int MB,
    int do_relu) {
    constexpr int BM = 128;
    constexpr int NT = NOUT / 16;        // n-tiles per warp: 8 / 4
    constexpr int A_BYTES = BM * 128;    // [128 rows][64 bf16 = 128B] = 16KB
    constexpr int B_BYTES = NOUT * 128;  // [NOUT rows][64 bf16 = 128B]
    extern __shared__ char smem[];
    char* A_HI = smem;
    char* A_LO = smem + A_BYTES;
    char* B_HI = smem + 2 * A_BYTES;
    char* B_LO = smem + 2 * A_BYTES + B_BYTES;

    // side dispatch
    const float* xdst; const float* mean; const float* Ws; const float* Wn;
    const float* bias; float* out; int M, bid;
    if ((int)blockIdx.x < nblkA) {
        xdst = xdA; mean = mnA; Ws = WsA; Wn = WnA; bias = bA; out = outA;
        M = MA; bid = blockIdx.x;
    } else {
        xdst = xdB; mean = mnB; Ws = WsB; Wn = WnB; bias = bB; out = outB;
        M = MB; bid = blockIdx.x - nblkA;
    }

    const int tid = threadIdx.x;
    const int w = tid >> 5;
    const int l = tid & 31;
    const int wm = w & 3;      // 4 warps along M (32 rows each)
    const int wn = w >> 2;     // 2 warps along N (NOUT/2 cols each)
    const int row0 = bid * BM;

    const uint32_t saAH = smem_u32(A_HI);
    const uint32_t saAL = smem_u32(A_LO);
    const uint32_t saBH = smem_u32(B_HI);
    const uint32_t saBL = smem_u32(B_LO);

    float acc[2][NT][4];
#pragma unroll
    for (int mt = 0; mt < 2; mt++)
#pragma unroll
        for (int nt = 0; nt < NT; nt++)
#pragma unroll
            for (int j = 0; j < 4; j++) acc[mt][nt][j] = 0.f;

    // staging indices
    const int ar = tid >> 1;             // A row handled by this thread
    const int ah = tid & 1;              // col half (32 fp32 each)
    constexpr int TPN = 256 / NOUT;      // threads per W column: 2 / 4
    constexpr int KB = 64 / TPN;         // k-span per thread: 32 / 16
    const int bn = tid % NOUT;
    const int bk0 = (tid / NOUT) * KB;

    // ldmatrix per-lane addresses (within-chunk, before adding kt offset)
    // A: row m = (l&15), col-half by (l>>4)
    const uint32_t a_m = (uint32_t)(l & 15);
    const uint32_t a_ch = (uint32_t)(l >> 4) * 8;
    // B: row n = nt*8 + (l&7), col-half by ((l>>3)&1)
    const uint32_t b_nl = (uint32_t)(l & 7);
    const uint32_t b_ch = (uint32_t)((l >> 3) & 1) * 8;

    for (int op = 0; op < 2; ++op) {
        const float* Xp = op ? mean : xdst;
        const float* Wp = op ? Wn : Ws;
        for (int ch = 0; ch < 2; ++ch) {
            const int kbase = ch * 64;
            __syncthreads();
            // ---- stage A chunk [128 x 64] hi/lo
            {
                const int gr = row0 + ar;
                const float* xr = Xp + (size_t)gr * DIN + kbase + ah * 32;
                const uint32_t obase = (uint32_t)(ar * 128 + ah * 64);
#pragma unroll
                for (int i = 0; i < 8; i++) {
                    float4 v = (gr < M)
                                   ? *reinterpret_cast<const float4*>(xr + 4 * i)
                                   : make_float4(0.f, 0.f, 0.f, 0.f);
                    __nv_bfloat16 h0 = __float2bfloat16(v.x);
                    __nv_bfloat16 h1 = __float2bfloat16(v.y);
                    __nv_bfloat16 h2 = __float2bfloat16(v.z);
                    __nv_bfloat16 h3 = __float2bfloat16(v.w);
                    uint32_t o = sw128(obase + 8 * i);
                    *reinterpret_cast<unsigned long long*>(A_HI + o) =
                        bfpack4(h0, h1, h2, h3);
                    *reinterpret_cast<unsigned long long*>(A_LO + o) = bfpack4(
                        __float2bfloat16(v.x - __bfloat162float(h0)),
                        __float2bfloat16(v.y - __bfloat162float(h1)),
                        __float2bfloat16(v.z - __bfloat162float(h2)),
                        __float2bfloat16(v.w - __bfloat162float(h3)));
                }
            }
            // ---- stage B chunk: W[k][n] -> smem [n][64k] hi/lo
            {
#pragma unroll
                for (int j = 0; j < KB / 4; j++) {
                    int k = bk0 + 4 * j;
                    const float* wp = Wp + (size_t)(kbase + k) * NOUT + bn;
                    float w0 = wp[0];
                    float w1 = wp[NOUT];
                    float w2 = wp[2 * NOUT];
                    float w3 = wp[3 * NOUT];
                    __nv_bfloat16 h0 = __float2bfloat16(w0);
                    __nv_bfloat16 h1 = __float2bfloat16(w1);
                    __nv_bfloat16 h2 = __float2bfloat16(w2);
                    __nv_bfloat16 h3 = __float2bfloat16(w3);
                    uint32_t o = sw128((uint32_t)(bn * 128 + k * 2));
                    *reinterpret_cast<unsigned long long*>(B_HI + o) =
                        bfpack4(h0, h1, h2, h3);
                    *reinterpret_cast<unsigned long long*>(B_LO + o) = bfpack4(
                        __float2bfloat16(w0 - __bfloat162float(h0)),
                        __float2bfloat16(w1 - __bfloat162float(h1)),
                        __float2bfloat16(w2 - __bfloat162float(h2)),
                        __float2bfloat16(w3 - __bfloat162float(h3)));
                }
            }
            __syncthreads();

            // ---- 3 passes x 4 k16-steps of mma
#pragma unroll
            for (int p = 0; p < 3; p++) {
                const uint32_t sa = (p == 2) ? saAL : saAH;
                const uint32_t sb = (p == 1) ? saBL : saBH;
#pragma unroll
                for (int kt = 0; kt < 4; kt++) {
                    uint32_t af[2][4];
#pragma unroll
                    for (int mt = 0; mt < 2; mt++) {
                        uint32_t r = (uint32_t)(wm * 32 + mt * 16) + a_m;
                        uint32_t c = (uint32_t)(kt * 16) + a_ch;
                        ldsm_x4(af[mt], sa + sw128(r * 128 + c * 2));
                    }
                    uint32_t bf[NT][2];
#pragma unroll
                    for (int nt = 0; nt < NT; nt++) {
                        uint32_t n = (uint32_t)(wn * (NOUT / 2) + nt * 8) + b_nl;
                        uint32_t c = (uint32_t)(kt * 16) + b_ch;
                        ldsm_x2(bf[nt], sb + sw128(n * 128 + c * 2));
                    }
#pragma unroll
                    for (int mt = 0; mt < 2; mt++)
#pragma unroll
                        for (int nt = 0; nt < NT; nt++)
                            mma16816(acc[mt][nt], af[mt], bf[nt]);
                }
            }
        }
    }

    // ---- epilogue: bias (+relu), direct to gmem
    const int gq = l >> 2;   // row within 16-tile: gq and gq+8
    const int tq = l & 3;    // col pair: tq*2, tq*2+1
#pragma unroll
    for (int mt = 0; mt < 2; mt++) {
        int r0g = row0 + wm * 32 + mt * 16 + gq;
#pragma unroll
        for (int nt = 0; nt < NT; nt++) {
            int col = wn * (NOUT / 2) + nt * 8 + tq * 2;
            float b0 = __ldg(&bias[col]);
            float b1 = __ldg(&bias[col + 1]);
            float d0 = acc[mt][nt][0] + b0;
            float d1 = acc[mt][nt][1] + b1;
            float d2 = acc[mt][nt][2] + b0;
            float d3 = acc[mt][nt][3] + b1;
            if (do_relu) {
                d0 = fmaxf(d0, 0.f);
                d1 = fmaxf(d1, 0.f);
                d2 = fmaxf(d2, 0.f);
                d3 = fmaxf(d3, 0.f);
            }
            if (r0g < M)
                *reinterpret_cast<float2*>(out + (size_t)r0g * NOUT + col) =
                    make_float2(d0, d1);
            if (r0g + 8 < M)
                *reinterpret_cast<float2*>(out + (size_t)(r0g + 8) * NOUT + col) =
                    make_float2(d2, d3);
        }
    }
}

// ---------------- host launch -----------------------------------------------
extern "C" void kernel_launch(void* const* d_in, const int* in_sizes, int n_in,
                              void* d_out, int out_size) {
    const float* x_user = (const float*)d_in[0];
    const float* x_song = (const float*)d_in[1];
    const int* us_src = (const int*)d_in[2];
    const int* us_dst = (const int*)d_in[3];
    const int* su_src = (const int*)d_in[4];
    const int* su_dst = (const int*)d_in[5];
    const float* W1_us_n = (const float*)d_in[6];
    const float* W1_us_s = (const float*)d_in[7];
    const float* b1_us = (const float*)d_in[8];
    const float* W1_su_n = (const float*)d_in[9];
    const float* W1_su_s = (const float*)d_in[10];
    const float* b1_su = (const float*)d_in[11];
    const float* W2_us_n = (const float*)d_in[12];
    const float* W2_us_s = (const float*)d_in[13];
    const float* b2_us = (const float*)d_in[14];
    const float* W2_su_n = (const float*)d_in[15];
    const float* W2_su_s = (const float*)d_in[16];
    const float* b2_su = (const float*)d_in[17];
    float* out = (float*)d_out;

    float *mean_user, *mean_song, *h_user, *h_song;
    int *cnt_user, *cnt_song, *off_user, *off_song, *fin_user, *fin_song;
    int *cur_user, *cur_song, *srt_us, *srt_su, *part;
    cudaGetSymbolAddress((void**)&mean_user, g_mean_user);
    cudaGetSymbolAddress((void**)&mean_song, g_mean_song);
    cudaGetSymbolAddress((void**)&h_user, g_h_user);
    cudaGetSymbolAddress((void**)&h_song, g_h_song);
    cudaGetSymbolAddress((void**)&cnt_user, g_cnt_user);
    cudaGetSymbolAddress((void**)&cnt_song, g_cnt_song);
    cudaGetSymbolAddress((void**)&off_user, g_off_user);
    cudaGetSymbolAddress((void**)&off_song, g_off_song);
    cudaGetSymbolAddress((void**)&fin_user, g_fin_user);
    cudaGetSymbolAddress((void**)&fin_song, g_fin_song);
    cudaGetSymbolAddress((void**)&cur_user, g_cur_user);
    cudaGetSymbolAddress((void**)&cur_song, g_cur_song);
    cudaGetSymbolAddress((void**)&srt_us, g_srt_us);
    cudaGetSymbolAddress((void**)&srt_su, g_srt_su);
    cudaGetSymbolAddress((void**)&part, g_part);

    const int NB_S = (NS + 1023) / 1024;  // 49
    const int NB_U = (NU + 1023) / 1024;  // 98

    const int SMEM1 = 2 * 128 * 128 + 2 * H1 * 128;  // 65536 B
    const int SMEM2 = 2 * 128 * 128 + 2 * H2 * 128;  // 49152 B
    cudaFuncSetAttribute(sage_gemm_mma<H1>,
                         cudaFuncAttributeMaxDynamicSharedMemorySize, SMEM1);
    cudaFuncSetAttribute(sage_gemm_mma<H2>,
                         cudaFuncAttributeMaxDynamicSharedMemorySize, SMEM2);

    // ---- CSR build
    zero_int2<<<(NU + 255) / 256, 256>>>(cnt_user, NU, cnt_song, NS);
    count_kernel<<<(NE + 255) / 256, 256>>>(us_dst, su_dst, cnt_song, cnt_user, NE);
    scan_block_dual<<<NB_S + NB_U, 1024>>>(cnt_song, off_song, NS, cnt_user,
                                           off_user, NU, part, NB_S);
    scan_partials_dual<<<1, 128>>>(part, NB_S, NB_U);
    scan_finish_dual<<<(NS + NU + 255) / 256, 256>>>(
        off_song, fin_song, cur_song, NS, off_user, fin_user, cur_user, NU,
        part, NB_S);
    bin_dual<<<(NE + 255) / 256, 256>>>(us_src, us_dst, su_src, su_dst, cur_song,
                                        cur_user, srt_us, srt_su, NE);

    const int naS = (NS + 127) / 128;  // 391
    const int naU = (NU + 127) / 128;  // 782

    // ---- layer 1
    gather_dual<<<(NS + NU + 7) / 8, 256>>>(x_user, srt_us, fin_song, mean_song,
                                            NS, x_song, srt_su, fin_user,
                                            mean_user, NU);
    sage_gemm_mma<H1><<<naS + naU, 256, SMEM1>>>(
        x_song, mean_song, W1_us_s, W1_us_n, b1_us, h_song, NS, naS, x_user,
        mean_user, W1_su_s, W1_su_n, b1_su, h_user, NU, 1);

    // ---- layer 2
    gather_dual<<<(NS + NU + 7) / 8, 256>>>(h_user, srt_us, fin_song, mean_song,
                                            NS, h_song, srt_su, fin_user,
                                            mean_user, NU);
    sage_gemm_mma<H2><<<naS + naU, 256, SMEM2>>>(
        h_song, mean_song, W2_us_s, W2_us_n, b2_us, out + (size_t)NU * H2, NS,
        naS, h_user, mean_user, W2_su_s, W2_su_n, b2_su, out, NU, 0);
}